// round 6
// baseline (speedup 1.0000x reference)
#include <cuda_runtime.h>
#include <cstdint>
#include <cstddef>

// ---------------- helpers ----------------
__device__ __forceinline__ uint32_t rnd_tf32(float f) {
    uint32_t r;
    asm("cvt.rna.tf32.f32 %0, %1;" : "=r"(r) : "f"(f));
    return r;
}

// m16n8k8 row.col f32.tf32.tf32.f32  (family-common PTX, works on plain sm_103)
#define MMA_TF32(c, a, b0, b1)                                                  \
    asm volatile("mma.sync.aligned.m16n8k8.row.col.f32.tf32.tf32.f32 "          \
                 "{%0,%1,%2,%3},{%4,%5,%6,%7},{%8,%9},{%0,%1,%2,%3};"           \
                 : "+f"((c)[0]), "+f"((c)[1]), "+f"((c)[2]), "+f"((c)[3])       \
                 : "r"((a)[0]), "r"((a)[1]), "r"((a)[2]), "r"((a)[3]),          \
                   "r"(b0), "r"(b1))

// ---------------- problem constants ----------------
static constexpr int BATCH = 16;
static constexpr int C     = 64;     // CIN == COUT
static constexpr int HW    = 112;
static constexpr int TH    = 8;      // tile h  -> M = 128 pixels per CTA
static constexpr int TW    = 16;     // tile w
static constexpr int RS    = 20;     // halo row stride (floats)
static constexpr int CPL   = 200;    // halo plane stride; 200 % 32 == 8 -> bank-perfect A loads

static constexpr int HALO_FLOATS = C * CPL;            // 12800
static constexpr int SMEM_SZ     = HALO_FLOATS * 4;    // 51200 B -> 4 CTAs/SM

__global__ void __launch_bounds__(256, 4)
conv3x3_tf32_mma(const float* __restrict__ x,
                 const float* __restrict__ wt,
                 const float* __restrict__ bias,
                 float* __restrict__ out)
{
    extern __shared__ float halo[];     // [cin][row(20)][col]

    const int tid  = threadIdx.x;
    const int lane = tid & 31;
    const int wid  = tid >> 5;
    const int wm   = wid >> 1;          // 0..3 : 2 h-rows each
    const int wn   = wid & 1;           // 0..1 : 32 couts each
    const int g    = lane >> 2;         // groupID 0..7
    const int t    = lane & 3;          // thread-in-group

    const int w0 = blockIdx.x * TW;
    const int h0 = blockIdx.y * TH;
    const int b  = blockIdx.z;

    // ---- halo load: 64 cin x 10 x 18, tf32-rounded, zero padded ----
    #pragma unroll 5
    for (int i = 0; i < 45; ++i) {      // 45*256 == 64*10*18 exactly
        int idx = tid + i * 256;
        int c   = idx / 180;
        int rem = idx - c * 180;
        int r   = rem / 18;
        int w   = rem - r * 18;
        int gh = h0 - 1 + r, gw = w0 - 1 + w;
        uint32_t v = 0u;
        if ((unsigned)gh < (unsigned)HW && (unsigned)gw < (unsigned)HW)
            v = rnd_tf32(x[(((size_t)b * C + c) * HW + gh) * HW + gw]);
        halo[c * CPL + r * RS + w] = __uint_as_float(v);
    }
    __syncthreads();

    float acc[2][4][4];                 // [mt][nt][creg]
    #pragma unroll
    for (int i = 0; i < 2; ++i)
        #pragma unroll
        for (int j = 0; j < 4; ++j)
            #pragma unroll
            for (int k = 0; k < 4; ++k) acc[i][j][k] = 0.f;

    // B fragment base: row (cin = 8s+t) -> k-row (8s+t)*9 + kpos; col co = wn*32 + nt*8 + g
    // wbk(kpos) = wt + (t*9 + kpos)*64 + wn*32 + g ; per s add s*8*9*64 = s*4608
    const float* wb = wt + ((size_t)t * 9) * 64 + wn * 32 + g;

    #pragma unroll 1
    for (int kpos = 0; kpos < 9; ++kpos) {
        const int kh = kpos / 3;
        const int kw = kpos - kh * 3;

        const char* ab = (const char*)halo
                       + ((size_t)t * CPL + (wm * 2 + kh) * RS + g + kw) * 4;
        const float* wk = wb + (size_t)kpos * 64;

        #pragma unroll
        for (int s = 0; s < 8; ++s) {
            // ---- A fragments from smem halo (bank-perfect scalar LDS) ----
            uint32_t A[2][4];
            #pragma unroll
            for (int mt = 0; mt < 2; ++mt) {
                const char* p = ab + s * 6400 + mt * 80;    // s*8 planes, mt rows
                A[mt][0] = *(const uint32_t*)(p);           // (w=g,   cin=8s+t)
                A[mt][1] = *(const uint32_t*)(p + 32);      // (w=g+8, cin=8s+t)
                A[mt][2] = *(const uint32_t*)(p + 3200);    // (w=g,   cin=8s+t+4)
                A[mt][3] = *(const uint32_t*)(p + 3232);    // (w=g+8, cin=8s+t+4)
            }
            // ---- B fragments straight from gmem (L1-resident weights) ----
            const float* ws = wk + (size_t)s * 4608;        // cin += 8s  (8*9*64)
            uint32_t Bf[8];
            #pragma unroll
            for (int nt = 0; nt < 4; ++nt) {
                Bf[2*nt]   = rnd_tf32(__ldg(ws + nt * 8));          // cin = 8s+t
                Bf[2*nt+1] = rnd_tf32(__ldg(ws + nt * 8 + 2304));   // cin = 8s+t+4 (+4*9*64)
            }

            #pragma unroll
            for (int mt = 0; mt < 2; ++mt)
                #pragma unroll
                for (int nt = 0; nt < 4; ++nt)
                    MMA_TF32(acc[mt][nt], A[mt], Bf[2*nt], Bf[2*nt+1]);
        }
    }

    // ---- epilogue ----
    #pragma unroll
    for (int nt = 0; nt < 4; ++nt) {
        const int co0 = wn * 32 + nt * 8 + 2 * t;
        const float bz0 = __ldg(bias + co0);
        const float bz1 = __ldg(bias + co0 + 1);
        #pragma unroll
        for (int mt = 0; mt < 2; ++mt) {
            const int h = h0 + wm * 2 + mt;
            float* p0 = out + (((size_t)b * C + co0) * HW + h) * HW + w0;
            float* p1 = p0 + (size_t)HW * HW;
            p0[g]     = acc[mt][nt][0] + bz0;   // w=g,   cout co0
            p1[g]     = acc[mt][nt][1] + bz1;   // w=g,   cout co0+1
            p0[g + 8] = acc[mt][nt][2] + bz0;   // w=g+8, cout co0
            p1[g + 8] = acc[mt][nt][3] + bz1;   // w=g+8, cout co0+1
        }
    }
}

extern "C" void kernel_launch(void* const* d_in, const int* in_sizes, int n_in,
                              void* d_out, int out_size)
{
    const float* x    = (const float*)d_in[0];
    const float* wt   = (const float*)d_in[1];
    const float* bias = (const float*)d_in[2];
    float* out = (float*)d_out;

    cudaFuncSetAttribute(conv3x3_tf32_mma,
                         cudaFuncAttributeMaxDynamicSharedMemorySize, SMEM_SZ);
    dim3 grid(HW / TW, HW / TH, BATCH);   // 7 x 14 x 16
    conv3x3_tf32_mma<<<grid, 256, SMEM_SZ>>>(x, wt, bias, out);
}

// round 7
// speedup vs baseline: 1.2715x; 1.2715x over previous
#include <cuda_runtime.h>
#include <cuda_fp16.h>
#include <cstdint>
#include <cstddef>

// ---------------- helpers ----------------
__device__ __forceinline__ uint32_t rnd_tf32(float f) {
    uint32_t r;
    asm("cvt.rna.tf32.f32 %0, %1;" : "=r"(r) : "f"(f));
    return r;
}

// m16n8k8 row.col f32.tf32.tf32.f32  (family-common PTX, works on plain sm_103)
#define MMA_TF32(c, a, b0, b1)                                                  \
    asm volatile("mma.sync.aligned.m16n8k8.row.col.f32.tf32.tf32.f32 "          \
                 "{%0,%1,%2,%3},{%4,%5,%6,%7},{%8,%9},{%0,%1,%2,%3};"           \
                 : "+f"((c)[0]), "+f"((c)[1]), "+f"((c)[2]), "+f"((c)[3])       \
                 : "r"((a)[0]), "r"((a)[1]), "r"((a)[2]), "r"((a)[3]),          \
                   "r"(b0), "r"(b1))

// ---------------- problem constants ----------------
static constexpr int BATCH = 16;
static constexpr int C     = 64;     // CIN == COUT
static constexpr int HW    = 112;
static constexpr int TH    = 8;      // tile h  -> M = 128 pixels per CTA
static constexpr int TW    = 16;     // tile w
static constexpr int RS    = 20;     // halo row stride (halfs)
static constexpr int CPLH  = 208;    // halo plane stride (halfs); word-stride 104 % 32 == 8 -> conflict-free

// smem layout (bytes): B2 double buffer then fp16 halo
static constexpr int B2_BYTES   = 2 * 16384;                 // 32768
static constexpr int HALO_BYTES = C * CPLH * 2;              // 26624
static constexpr int SMEM_SZ    = B2_BYTES + HALO_BYTES;     // 59392 -> 3 CTAs/SM

__global__ void __launch_bounds__(256, 3)
conv3x3_tf32_mma(const float* __restrict__ x,
                 const float* __restrict__ wt,
                 const float* __restrict__ bias,
                 float* __restrict__ out)
{
    extern __shared__ char smem[];
    float*  B2   = (float*)smem;                  // [buf][frag-order 4096 floats]
    __half* halo = (__half*)(smem + B2_BYTES);    // [cin][row(20)][col] fp16

    const int tid  = threadIdx.x;
    const int lane = tid & 31;
    const int wid  = tid >> 5;
    const int wm   = wid >> 1;          // 0..3 : 2 h-rows each
    const int wn   = wid & 1;           // 0..1 : 32 couts each
    const int g    = lane >> 2;         // groupID 0..7
    const int t    = lane & 3;          // thread-in-group

    const int w0 = blockIdx.x * TW;
    const int h0 = blockIdx.y * TH;
    const int b  = blockIdx.z;

    // ---- halo load: 64 cin x 10 x 18 -> fp16 (same mantissa as tf32), zero padded ----
    #pragma unroll 5
    for (int i = 0; i < 45; ++i) {      // 45*256 == 64*10*18 exactly
        int idx = tid + i * 256;
        int c   = idx / 180;
        int rem = idx - c * 180;
        int r   = rem / 18;
        int w   = rem - r * 18;
        int gh = h0 - 1 + r, gw = w0 - 1 + w;
        float v = 0.f;
        if ((unsigned)gh < (unsigned)HW && (unsigned)gw < (unsigned)HW)
            v = x[(((size_t)b * C + c) * HW + gh) * HW + gw];
        halo[c * CPLH + r * RS + w] = __float2half_rn(v);
    }

    float acc[2][4][4];                 // [mt][nt][creg]
    #pragma unroll
    for (int i = 0; i < 2; ++i)
        #pragma unroll
        for (int j = 0; j < 4; ++j)
            #pragma unroll
            for (int k = 0; k < 4; ++k) acc[i][j][k] = 0.f;

    // builder roles (B staging): warp wid owns cin slice s=wid
    const int bt = lane & 3;
    const int bg = lane >> 2;

    // ---- prologue: stage kpos=0 into buf0, then one barrier (also covers halo) ----
    {
        const float* r0 = wt + ((size_t)(wid * 8 + bt)     * 9 + 0) * 64;
        const float* r1 = wt + ((size_t)(wid * 8 + bt + 4) * 9 + 0) * 64;
        #pragma unroll
        for (int wnn = 0; wnn < 2; ++wnn)
            #pragma unroll
            for (int nt = 0; nt < 4; ++nt) {
                int co = wnn * 32 + nt * 8 + bg;
                float2 v = make_float2(__uint_as_float(rnd_tf32(r0[co])),
                                       __uint_as_float(rnd_tf32(r1[co])));
                *(float2*)((char*)B2 + (wid * 2 + wnn) * 1024 + (nt >> 1) * 512
                                     + lane * 16 + (nt & 1) * 8) = v;
            }
    }
    __syncthreads();

    #pragma unroll 1
    for (int kpos = 0; kpos < 9; ++kpos) {
        const int kh  = kpos / 3;
        const int kw  = kpos - kh * 3;
        const int buf = kpos & 1;

        // ---- stage NEXT kpos into the other buffer (overlaps with compute below) ----
        if (kpos < 8) {
            const float* r0 = wt + ((size_t)(wid * 8 + bt)     * 9 + kpos + 1) * 64;
            const float* r1 = wt + ((size_t)(wid * 8 + bt + 4) * 9 + kpos + 1) * 64;
            #pragma unroll
            for (int wnn = 0; wnn < 2; ++wnn)
                #pragma unroll
                for (int nt = 0; nt < 4; ++nt) {
                    int co = wnn * 32 + nt * 8 + bg;
                    float2 v = make_float2(__uint_as_float(rnd_tf32(r0[co])),
                                           __uint_as_float(rnd_tf32(r1[co])));
                    *(float2*)((char*)B2 + (buf ^ 1) * 16384
                                         + (wid * 2 + wnn) * 1024 + (nt >> 1) * 512
                                         + lane * 16 + (nt & 1) * 8) = v;
                }
        }

        // ---- compute kpos from buf: 8 cin-slices of K8 ----
        const __half* ab = halo + t * CPLH + (wm * 2 + kh) * RS + g + kw;
        const char*   bb = (const char*)B2 + buf * 16384 + wn * 1024 + lane * 16;

        #pragma unroll
        for (int s = 0; s < 8; ++s) {
            uint32_t A[2][4];
            #pragma unroll
            for (int mt = 0; mt < 2; ++mt) {
                const __half* p = ab + s * 8 * CPLH + mt * RS;
                A[mt][0] = __float_as_uint(__half2float(p[0]));          // w=g,   cin=8s+t
                A[mt][1] = __float_as_uint(__half2float(p[8]));          // w=g+8, cin=8s+t
                A[mt][2] = __float_as_uint(__half2float(p[4 * CPLH]));   // w=g,   cin=8s+t+4
                A[mt][3] = __float_as_uint(__half2float(p[4 * CPLH + 8]));
            }
            uint32_t Bf[8];
            *(uint4*)&Bf[0] = *(const uint4*)(bb + s * 2048);        // nt0, nt1
            *(uint4*)&Bf[4] = *(const uint4*)(bb + s * 2048 + 512);  // nt2, nt3

            #pragma unroll
            for (int mt = 0; mt < 2; ++mt)
                #pragma unroll
                for (int nt = 0; nt < 4; ++nt)
                    MMA_TF32(acc[mt][nt], A[mt], Bf[2 * nt], Bf[2 * nt + 1]);
        }
        __syncthreads();    // staging of buf^1 done; readers of buf done
    }

    // ---- epilogue ----
    #pragma unroll
    for (int nt = 0; nt < 4; ++nt) {
        const int co0 = wn * 32 + nt * 8 + 2 * t;
        const float bz0 = __ldg(bias + co0);
        const float bz1 = __ldg(bias + co0 + 1);
        #pragma unroll
        for (int mt = 0; mt < 2; ++mt) {
            const int h = h0 + wm * 2 + mt;
            float* p0 = out + (((size_t)b * C + co0) * HW + h) * HW + w0;
            float* p1 = p0 + (size_t)HW * HW;
            p0[g]     = acc[mt][nt][0] + bz0;   // w=g,   cout co0
            p1[g]     = acc[mt][nt][1] + bz1;   // w=g,   cout co0+1
            p0[g + 8] = acc[mt][nt][2] + bz0;   // w=g+8, cout co0
            p1[g + 8] = acc[mt][nt][3] + bz1;   // w=g+8, cout co0+1
        }
    }
}

extern "C" void kernel_launch(void* const* d_in, const int* in_sizes, int n_in,
                              void* d_out, int out_size)
{
    const float* x    = (const float*)d_in[0];
    const float* wt   = (const float*)d_in[1];
    const float* bias = (const float*)d_in[2];
    float* out = (float*)d_out;

    cudaFuncSetAttribute(conv3x3_tf32_mma,
                         cudaFuncAttributeMaxDynamicSharedMemorySize, SMEM_SZ);
    dim3 grid(HW / TW, HW / TH, BATCH);   // 7 x 14 x 16
    conv3x3_tf32_mma<<<grid, 256, SMEM_SZ>>>(x, wt, bias, out);
}

// round 8
// speedup vs baseline: 2.3634x; 1.8587x over previous
#include <cuda_runtime.h>
#include <cuda_fp16.h>
#include <cstdint>
#include <cstddef>

// m16n8k16 row.col f32.f16.f16.f32 (family-common PTX, works on plain sm_103)
#define MMA_F16(c, a, b0, b1)                                                   \
    asm volatile("mma.sync.aligned.m16n8k16.row.col.f32.f16.f16.f32 "           \
                 "{%0,%1,%2,%3},{%4,%5,%6,%7},{%8,%9},{%0,%1,%2,%3};"           \
                 : "+f"((c)[0]), "+f"((c)[1]), "+f"((c)[2]), "+f"((c)[3])       \
                 : "r"((a)[0]), "r"((a)[1]), "r"((a)[2]), "r"((a)[3]),          \
                   "r"(b0), "r"(b1))

// ---------------- problem constants ----------------
static constexpr int BATCH = 16;
static constexpr int C     = 64;     // CIN == COUT
static constexpr int HW    = 112;
static constexpr int TH    = 8;      // tile h  -> M = 128 pixels per CTA
static constexpr int TW    = 16;     // tile w

// halo: 32 channel-pairs x 10 rows x 18 cols of half2, row stride 20 words,
// plane stride 200 words (200 % 32 == 8 -> conflict-free A loads)
static constexpr int PRS   = 20;     // row stride in words (half2)
static constexpr int PPL   = 200;    // pair-plane stride in words
static constexpr int SMEM_SZ = 32 * PPL * 4;   // 25600 B -> 4 CTAs/SM

// fragment-ordered fp16 weights: 288 chunks x 512 B = 73728 B
__device__ uint32_t g_B2[36864];

// ---- prep kernel: wt[fp32, (cin*9+kpos) x 64] -> fragment-ordered fp16 pairs ----
__global__ void __launch_bounds__(256, 1)
prep_weights(const float* __restrict__ wt)
{
    int idx    = blockIdx.x * 256 + threadIdx.x;   // 0..36863
    int chunk  = idx >> 7;
    int within = idx & 127;
    int lane = within >> 2, r = within & 3;
    int h2   = chunk & 1;
    int wn   = (chunk >> 1) & 1;
    int s    = (chunk >> 2) & 3;
    int kpos = chunk >> 4;                          // 0..8
    int nt   = h2 * 2 + (r >> 1);
    int breg = r & 1;
    int g = lane >> 2, t = lane & 3;
    int co  = wn * 32 + nt * 8 + g;
    int cin = s * 16 + 2 * t + breg * 8;
    __half lo = __float2half_rn(wt[((size_t)cin * 9 + kpos) * 64 + co]);
    __half hi = __float2half_rn(wt[((size_t)(cin + 1) * 9 + kpos) * 64 + co]);
    __half2 v = __halves2half2(lo, hi);
    g_B2[idx] = *(uint32_t*)&v;
}

__global__ void __launch_bounds__(256, 4)
conv3x3_f16_mma(const float* __restrict__ x,
                const float* __restrict__ bias,
                float* __restrict__ out)
{
    extern __shared__ uint32_t halo32[];            // [pair][row(20)][col] half2
    __half* haloh = (__half*)halo32;

    const int tid  = threadIdx.x;
    const int lane = tid & 31;
    const int wid  = tid >> 5;
    const int wm   = wid >> 1;          // 0..3 : 2 h-rows each
    const int wn   = wid & 1;           // 0..1 : 32 couts each
    const int g    = lane >> 2;         // groupID 0..7
    const int t    = lane & 3;          // thread-in-group

    const int w0 = blockIdx.x * TW;
    const int h0 = blockIdx.y * TH;
    const int b  = blockIdx.z;

    // ---- halo load: 64 cin x 10 x 18 -> fp16 channel-pair layout, zero padded ----
    #pragma unroll 5
    for (int i = 0; i < 45; ++i) {      // 45*256 == 64*10*18 exactly
        int idx = tid + i * 256;
        int c   = idx / 180;
        int rem = idx - c * 180;
        int r   = rem / 18;
        int w   = rem - r * 18;
        int gh = h0 - 1 + r, gw = w0 - 1 + w;
        float v = 0.f;
        if ((unsigned)gh < (unsigned)HW && (unsigned)gw < (unsigned)HW)
            v = x[(((size_t)b * C + c) * HW + gh) * HW + gw];
        haloh[(c >> 1) * (2 * PPL) + r * (2 * PRS) + 2 * w + (c & 1)] = __float2half_rn(v);
    }
    __syncthreads();

    float acc[2][4][4];                 // [mt][nt][creg]
    #pragma unroll
    for (int i = 0; i < 2; ++i)
        #pragma unroll
        for (int j = 0; j < 4; ++j)
            #pragma unroll
            for (int k = 0; k < 4; ++k) acc[i][j][k] = 0.f;

    #pragma unroll 1
    for (int kpos = 0; kpos < 9; ++kpos) {
        const int kh = kpos / 3;
        const int kw = kpos - kh * 3;

        // A base: pair = s*8 + t (+4), row = wm*2 + mt + kh, col = (g|g+8) + kw
        const uint32_t* aw = halo32 + t * PPL + (wm * 2 + kh) * PRS + g + kw;
        // B base: chunk index ((kpos*4+s)*2+wn)*2 + h2, 32 uint4 per chunk
        const uint4* bq = (const uint4*)g_B2 + ((size_t)(kpos * 4 * 2 + wn) * 2) * 32 + lane;

        #pragma unroll
        for (int s = 0; s < 4; ++s) {
            uint32_t A[2][4];
            #pragma unroll
            for (int mt = 0; mt < 2; ++mt) {
                const uint32_t* p = aw + s * 8 * PPL + mt * PRS;
                A[mt][0] = p[0];            // pair t,   w=g
                A[mt][1] = p[8];            // pair t,   w=g+8
                A[mt][2] = p[4 * PPL];      // pair t+4, w=g
                A[mt][3] = p[4 * PPL + 8];  // pair t+4, w=g+8
            }
            uint32_t Bf[8];
            *(uint4*)&Bf[0] = __ldg(bq + (size_t)s * 4 * 32);        // h2=0: nt0,nt1
            *(uint4*)&Bf[4] = __ldg(bq + (size_t)s * 4 * 32 + 32);   // h2=1: nt2,nt3

            #pragma unroll
            for (int mt = 0; mt < 2; ++mt)
                #pragma unroll
                for (int nt = 0; nt < 4; ++nt)
                    MMA_F16(acc[mt][nt], A[mt], Bf[2 * nt], Bf[2 * nt + 1]);
        }
    }

    // ---- epilogue ----
    #pragma unroll
    for (int nt = 0; nt < 4; ++nt) {
        const int co0 = wn * 32 + nt * 8 + 2 * t;
        const float bz0 = __ldg(bias + co0);
        const float bz1 = __ldg(bias + co0 + 1);
        #pragma unroll
        for (int mt = 0; mt < 2; ++mt) {
            const int h = h0 + wm * 2 + mt;
            float* p0 = out + (((size_t)b * C + co0) * HW + h) * HW + w0;
            float* p1 = p0 + (size_t)HW * HW;
            p0[g]     = acc[mt][nt][0] + bz0;   // w=g,   cout co0
            p1[g]     = acc[mt][nt][1] + bz1;   // w=g,   cout co0+1
            p0[g + 8] = acc[mt][nt][2] + bz0;   // w=g+8, cout co0
            p1[g + 8] = acc[mt][nt][3] + bz1;   // w=g+8, cout co0+1
        }
    }
}

extern "C" void kernel_launch(void* const* d_in, const int* in_sizes, int n_in,
                              void* d_out, int out_size)
{
    const float* x    = (const float*)d_in[0];
    const float* wt   = (const float*)d_in[1];
    const float* bias = (const float*)d_in[2];
    float* out = (float*)d_out;

    prep_weights<<<144, 256>>>(wt);     // 144*256 == 36864 exactly

    cudaFuncSetAttribute(conv3x3_f16_mma,
                         cudaFuncAttributeMaxDynamicSharedMemorySize, SMEM_SZ);
    dim3 grid(HW / TW, HW / TH, BATCH);   // 7 x 14 x 16
    conv3x3_f16_mma<<<grid, 256, SMEM_SZ>>>(x, bias, out);
}